// round 8
// baseline (speedup 1.0000x reference)
#include <cuda_runtime.h>

#define NB 512
#define NG 100
#define NP 100
#define NE 128
#define NH 8
#define NKD 16
#define LDP 132     // padded stride: enc / k / v / WT (floats)
#define LDW 132
#define LDQ 128     // q tile stride (broadcast-read only)
#define NTHR 768

// smem layout (floats)
#define S_ENC 0
#define S_K   13200
#define S_WS  26400    // 24 x 104
#define S_Q0  28896    // 128 ; pad to 30096 (WT = 128x132 spans [13200,30096))
#define S_V   30096
#define S_Q   43296
#define SM_FLOATS 56096   // 224384 B

typedef unsigned long long u64;

__device__ __forceinline__ void fma2(u64& d, u64 a, u64 b) {
    asm("fma.rn.f32x2 %0, %1, %2, %0;" : "+l"(d) : "l"(a), "l"(b));
}
__device__ __forceinline__ u64 add2(u64 a, u64 b) {
    u64 d; asm("add.rn.f32x2 %0, %1, %2;" : "=l"(d) : "l"(a), "l"(b)); return d;
}
__device__ __forceinline__ u64 pk(float lo, float hi) {
    u64 d; asm("mov.b64 %0, {%1, %2};" : "=l"(d) : "f"(lo), "f"(hi)); return d;
}
__device__ __forceinline__ float f2sum(u64 a) {
    float lo, hi; asm("mov.b64 {%0, %1}, %2;" : "=f"(lo), "=f"(hi) : "l"(a));
    return lo + hi;
}

// Transpose 128x128 weight into smem WT[n][e]=W[e][n] (768 threads).
__device__ __forceinline__ void fillWT(const float* __restrict__ W,
                                       float* __restrict__ WT, int t) {
    for (int idx = t; idx < 4096; idx += NTHR) {
        int n = idx & 127, e = (idx >> 7) * 4;
        float4 v;
        v.x = __ldg(W + (e + 0) * NE + n);
        v.y = __ldg(W + (e + 1) * NE + n);
        v.z = __ldg(W + (e + 2) * NE + n);
        v.w = __ldg(W + (e + 3) * NE + n);
        *(float4*)(WT + n * LDW + e) = v;
    }
}

// acc[i][j] += A[min(mg*9+i,99)][:] . WT[n0+32j][:], e-len 128, f32x2 packed.
__device__ __forceinline__ void gemm9(const float* __restrict__ A, int lda,
                                      const float* __restrict__ WT,
                                      u64 (&acc)[9][2], int n0, int mg) {
    const ulonglong2* wp0 = (const ulonglong2*)(WT + n0 * LDW);
    const ulonglong2* wp1 = (const ulonglong2*)(WT + (n0 + 32) * LDW);
    const float* ap[9];
    #pragma unroll
    for (int i = 0; i < 9; ++i) {
        int m = mg * 9 + i; if (m > 99) m = 99;   // clamped: result discarded
        ap[i] = A + m * lda;
    }
    #pragma unroll 2
    for (int e4 = 0; e4 < 32; ++e4) {
        ulonglong2 w0 = wp0[e4], w1 = wp1[e4];
        #pragma unroll
        for (int i = 0; i < 9; ++i) {
            ulonglong2 a = *(const ulonglong2*)(ap[i] + 4 * e4);
            fma2(acc[i][0], a.x, w0.x); fma2(acc[i][0], a.y, w0.y);
            fma2(acc[i][1], a.x, w1.x); fma2(acc[i][1], a.y, w1.y);
        }
    }
}

__global__ __launch_bounds__(NTHR, 1)
void fused_attn_kernel(
    const float* __restrict__ in1, const float* __restrict__ in2,
    const float* __restrict__ rem, const float* __restrict__ mask,
    const float* __restrict__ enc, const float* __restrict__ Wq,
    const float* __restrict__ Wk, const float* __restrict__ Wv,
    const float* __restrict__ Wc, const float* __restrict__ bc,
    float* __restrict__ out)
{
    extern __shared__ float sm[];
    float* s_enc = sm + S_ENC;
    float* s_k   = sm + S_K;      // k / mh ; WT alias spills through ws+q0+pad
    float* s_ws  = sm + S_WS;
    float* s_q0  = sm + S_Q0;
    float* s_v   = sm + S_V;
    float* s_q   = sm + S_Q;      // input2 -> q -> out_concat (stride 128)
    float* s_wt  = s_k;           // alias

    const int b    = blockIdx.x;
    const int t    = threadIdx.x;
    const int lane = t & 31;
    const int warp = t >> 5;            // 0..23
    const int mg   = warp >> 1;         // 0..11 (9 rows each)
    const int n0   = (warp & 1) * 64 + lane;   // owns cols n0, n0+32

    const float* encb  = enc  + (size_t)b * NP * NE;
    const float* in2b  = in2  + (size_t)b * NG * NE;
    const float* maskb = mask + (size_t)b * NG * NP;
    const float* remb  = rem  + (size_t)b * NG;

    u64 acc[9][2];

    // ---------------- Phase 1: stage enc + input2, compute q0 ----------------
    for (int idx = t; idx < NP * NE; idx += NTHR)
        s_enc[(idx >> 7) * LDP + (idx & 127)] = encb[idx];
    for (int idx = t; idx < NG * NE; idx += NTHR)
        s_q[idx] = in2b[idx];
    if (t < NE) {
        const float* i1 = in1 + (size_t)b * NE;
        float s = 0.f;
        #pragma unroll 8
        for (int e = 0; e < NE; ++e) s += i1[e] * __ldg(Wq + e * NE + t);
        s_q0[t] = s;
    }
    __syncthreads();                              // S1

    // ---------------- q-pass: q = [in1 | in2 | rem] @ Wq ----------------
    {
        float rq0a = s_q0[n0], rq0b = s_q0[n0 + 32];
        float rwla = __ldg(Wq + 2 * NE * NE + n0);
        float rwlb = __ldg(Wq + 2 * NE * NE + n0 + 32);
        __syncthreads();                          // S2: q0 reads done before WT spill
        fillWT(Wq + NE * NE, s_wt, t);            // rows 128..255 (input2 part)
        __syncthreads();                          // S3
        #pragma unroll
        for (int i = 0; i < 9; ++i) { acc[i][0] = 0ull; acc[i][1] = 0ull; }
        gemm9(s_q, LDQ, s_wt, acc, n0, mg);
        __syncthreads();                          // S4: WT + staged-input2 reads done
        #pragma unroll
        for (int i = 0; i < 9; ++i) {
            int m = mg * 9 + i;
            if (m < NG) {
                float rv = __ldg(remb + m);
                s_q[m * LDQ + n0]      = f2sum(acc[i][0]) + rq0a + rv * rwla;
                s_q[m * LDQ + n0 + 32] = f2sum(acc[i][1]) + rq0b + rv * rwlb;
            }
        }
    }

    // ---------------- v-pass: v = enc @ Wv ----------------
    fillWT(Wv, s_wt, t);                          // WT reads done at S4
    __syncthreads();                              // S5
    #pragma unroll
    for (int i = 0; i < 9; ++i) { acc[i][0] = 0ull; acc[i][1] = 0ull; }
    gemm9(s_enc, LDP, s_wt, acc, n0, mg);
    #pragma unroll
    for (int i = 0; i < 9; ++i) {
        int m = mg * 9 + i;
        if (m < NP) {
            s_v[m * LDP + n0]      = f2sum(acc[i][0]);
            s_v[m * LDP + n0 + 32] = f2sum(acc[i][1]);
        }
    }
    __syncthreads();                              // S6

    // ---------------- k-pass: k = enc @ Wk ----------------
    fillWT(Wk, s_wt, t);
    __syncthreads();                              // S7
    #pragma unroll
    for (int i = 0; i < 9; ++i) { acc[i][0] = 0ull; acc[i][1] = 0ull; }
    gemm9(s_enc, LDP, s_wt, acc, n0, mg);
    __syncthreads();                              // S8: WT reads done before k overwrites
    #pragma unroll
    for (int i = 0; i < 9; ++i) {
        int m = mg * 9 + i;
        if (m < NP) {
            s_k[m * LDP + n0]      = f2sum(acc[i][0]);
            s_k[m * LDP + n0 + 32] = f2sum(acc[i][1]);
        }
    }
    __syncthreads();                              // S9

    // ---------------- Phase 4: multi-head attention ----------------
    for (int task = warp; task < (NG / 2) * NH; task += 24) {
        int h  = task & 7;
        int gp = task >> 3;
        int g0 = 2 * gp, g1 = g0 + 1;
        const ulonglong2* qp0 = (const ulonglong2*)(s_q + g0 * LDQ + h * NKD);
        const ulonglong2* qp1 = (const ulonglong2*)(s_q + g1 * LDQ + h * NKD);

        // QK in two head-dim halves (keeps q live-set small)
        u64 x0[4] = {0,0,0,0}, x1[4] = {0,0,0,0};
        #pragma unroll
        for (int half = 0; half < 2; ++half) {
            ulonglong2 qa0 = qp0[2 * half], qa1 = qp0[2 * half + 1];
            ulonglong2 qb0 = qp1[2 * half], qb1 = qp1[2 * half + 1];
            #pragma unroll
            for (int r = 0; r < 4; ++r) {
                int p = lane + 32 * r;   // p<=127: reads in-bounds garbage rows, masked later
                const ulonglong2* kp = (const ulonglong2*)(s_k + p * LDP + h * NKD);
                ulonglong2 k0 = kp[2 * half], k1 = kp[2 * half + 1];
                fma2(x0[r], qa0.x, k0.x); fma2(x0[r], qa0.y, k0.y);
                fma2(x0[r], qa1.x, k1.x); fma2(x0[r], qa1.y, k1.y);
                fma2(x1[r], qb0.x, k0.x); fma2(x1[r], qb0.y, k0.y);
                fma2(x1[r], qb1.x, k1.x); fma2(x1[r], qb1.y, k1.y);
            }
        }

        float s0[4], s1[4];
        float mx0 = -3e38f, mx1 = -3e38f;
        #pragma unroll
        for (int r = 0; r < 4; ++r) {
            int p = lane + 32 * r;
            float a0 = -3e38f, a1 = -3e38f;
            if (p < NP) {
                a0 = f2sum(x0[r]) * 0.25f + __ldg(maskb + g0 * NP + p);
                a1 = f2sum(x1[r]) * 0.25f + __ldg(maskb + g1 * NP + p);
            }
            s0[r] = a0; s1[r] = a1;
            mx0 = fmaxf(mx0, a0); mx1 = fmaxf(mx1, a1);
        }
        #pragma unroll
        for (int o = 16; o; o >>= 1) {
            mx0 = fmaxf(mx0, __shfl_xor_sync(0xffffffffu, mx0, o));
            mx1 = fmaxf(mx1, __shfl_xor_sync(0xffffffffu, mx1, o));
        }
        float sum0 = 0.f, sum1 = 0.f;
        #pragma unroll
        for (int r = 0; r < 4; ++r) {
            float e0 = (s0[r] > -1e37f) ? __expf(s0[r] - mx0) : 0.f;
            float e1 = (s1[r] > -1e37f) ? __expf(s1[r] - mx1) : 0.f;
            s0[r] = e0; s1[r] = e1; sum0 += e0; sum1 += e1;
        }
        #pragma unroll
        for (int o = 16; o; o >>= 1) {
            sum0 += __shfl_xor_sync(0xffffffffu, sum0, o);
            sum1 += __shfl_xor_sync(0xffffffffu, sum1, o);
        }
        float inv0 = 1.f / sum0, inv1 = 1.f / sum1;

        // AV: two per-g passes over one 104-slot ws buffer
        float* w0 = s_ws + warp * 104;
        int c4 = lane >> 3, pgl = lane & 7;
        #pragma unroll
        for (int gsel = 0; gsel < 2; ++gsel) {
            #pragma unroll
            for (int r = 0; r < 4; ++r) {
                int p = lane + 32 * r;
                if (p < NP) w0[p] = gsel ? s1[r] * inv1 : s0[r] * inv0;
            }
            __syncwarp();
            u64 o0 = 0, o1 = 0;
            #pragma unroll
            for (int pp = 0; pp < 13; ++pp) {
                int p = pgl + 8 * pp;
                if (p < NP) {
                    ulonglong2 vv = *((const ulonglong2*)(s_v + p * LDP + h * NKD) + c4);
                    u64 aa = pk(w0[p], w0[p]);
                    fma2(o0, aa, vv.x);
                    fma2(o1, aa, vv.y);
                }
            }
            #pragma unroll
            for (int o = 4; o; o >>= 1) {
                o0 = add2(o0, __shfl_xor_sync(0xffffffffu, o0, o));
                o1 = add2(o1, __shfl_xor_sync(0xffffffffu, o1, o));
            }
            if (pgl == 0) {
                ulonglong2 r0; r0.x = o0; r0.y = o1;
                *((ulonglong2*)(s_q + (gsel ? g1 : g0) * LDQ + h * NKD + 4 * c4)) = r0;
            }
            __syncwarp();
        }
    }
    __syncthreads();                              // S10

    // ---------------- Phase 5: mh = out_concat @ Wc + bc -> s_k -------------
    fillWT(Wc, s_wt, t);                          // clobbers k + ws + q0 (all dead)
    __syncthreads();                              // S11
    {
        float rbca = __ldg(bc + n0), rbcb = __ldg(bc + n0 + 32);
        #pragma unroll
        for (int i = 0; i < 9; ++i) { acc[i][0] = 0ull; acc[i][1] = 0ull; }
        gemm9(s_q, LDQ, s_wt, acc, n0, mg);
        __syncthreads();                          // S12: WT reads done before mh overwrites
        #pragma unroll
        for (int i = 0; i < 9; ++i) {
            int m = mg * 9 + i;
            if (m < NG) {
                s_k[m * LDP + n0]      = f2sum(acc[i][0]) + rbca;
                s_k[m * LDP + n0 + 32] = f2sum(acc[i][1]) + rbcb;
            }
        }
    }
    __syncthreads();                              // S13

    // ---------------- Phase 6: pointer scores + clipped softmax -------------
    const float invsq = 0.08838834764831845f;     // 1/sqrt(128)
    float* outb = out + (size_t)b * NG * NP;
    for (int t6 = warp; t6 < NG / 2; t6 += 24) {  // 2 g per task
        int g0 = 2 * t6, g1 = g0 + 1;
        u64 pacc[2][4];
        #pragma unroll
        for (int g = 0; g < 2; ++g)
            #pragma unroll
            for (int r = 0; r < 4; ++r) pacc[g][r] = 0ull;
        const ulonglong2* ep[4];
        #pragma unroll
        for (int r = 0; r < 4; ++r)
            ep[r] = (const ulonglong2*)(s_enc + (lane + 32 * r) * LDP);  // p<=127 in-bounds
        const ulonglong2* mp0 = (const ulonglong2*)(s_k + g0 * LDP);
        const ulonglong2* mp1 = (const ulonglong2*)(s_k + g1 * LDP);
        #pragma unroll 2
        for (int e4 = 0; e4 < 32; ++e4) {
            ulonglong2 m0 = mp0[e4], m1 = mp1[e4];
            #pragma unroll
            for (int r = 0; r < 4; ++r) {
                ulonglong2 ea = ep[r][e4];
                fma2(pacc[0][r], m0.x, ea.x); fma2(pacc[0][r], m0.y, ea.y);
                fma2(pacc[1][r], m1.x, ea.x); fma2(pacc[1][r], m1.y, ea.y);
            }
        }
        #pragma unroll
        for (int g = 0; g < 2; ++g) {
            int gi = g0 + g;
            float sc[4]; float mx = -3e38f;
            #pragma unroll
            for (int r = 0; r < 4; ++r) {
                int p = lane + 32 * r;
                float s = -3e38f;
                if (p < NP)
                    s = 10.f * tanhf(f2sum(pacc[g][r]) * invsq) + __ldg(maskb + gi * NP + p);
                sc[r] = s; mx = fmaxf(mx, s);
            }
            #pragma unroll
            for (int o = 16; o; o >>= 1)
                mx = fmaxf(mx, __shfl_xor_sync(0xffffffffu, mx, o));
            float sum = 0.f;
            #pragma unroll
            for (int r = 0; r < 4; ++r) {
                float e_ = (sc[r] > -1e37f) ? __expf(sc[r] - mx) : 0.f;
                sc[r] = e_; sum += e_;
            }
            #pragma unroll
            for (int o = 16; o; o >>= 1)
                sum += __shfl_xor_sync(0xffffffffu, sum, o);
            float inv = 1.f / sum;
            #pragma unroll
            for (int r = 0; r < 4; ++r) {
                int p = lane + 32 * r;
                if (p < NP) outb[gi * NP + p] = sc[r] * inv;
            }
        }
    }
}

extern "C" void kernel_launch(void* const* d_in, const int* in_sizes, int n_in,
                              void* d_out, int out_size)
{
    const float* in1  = (const float*)d_in[0];
    const float* in2  = (const float*)d_in[1];
    const float* rem  = (const float*)d_in[2];
    const float* mask = (const float*)d_in[3];
    const float* enc  = (const float*)d_in[4];
    const float* Wq   = (const float*)d_in[5];
    const float* Wk   = (const float*)d_in[6];
    const float* Wv   = (const float*)d_in[7];
    const float* Wc   = (const float*)d_in[8];
    const float* bc   = (const float*)d_in[9];
    float* out = (float*)d_out;

    size_t smem = (size_t)SM_FLOATS * sizeof(float);  // 224384 B
    cudaFuncSetAttribute(fused_attn_kernel,
                         cudaFuncAttributeMaxDynamicSharedMemorySize, (int)smem);
    fused_attn_kernel<<<NB, NTHR, smem>>>(in1, in2, rem, mask, enc,
                                          Wq, Wk, Wv, Wc, bc, out);
}